// round 7
// baseline (speedup 1.0000x reference)
#include <cuda_runtime.h>
#include <cuda_bf16.h>
#include <cstdint>
#include <cstddef>

// ---------------- problem constants ----------------
#define N_TOK   32768      // B*L
#define DIM     768
#define NE      16         // experts
#define CAP     4096       // capacity per expert
#define F_EXP   3072
#define NCAT    6144       // 2*F_EXP (gate|up concat)
#define F_SH    1536
#define NCAT_SH 3072       // 2*F_SH

// ---------------- scratch (device globals; no allocations allowed) ----------
__device__ float        g_scores[(size_t)NE * N_TOK];          // [e][t]
__device__ unsigned int g_thresh[NE];
__device__ int          g_cnt[NE];
__device__ int          g_ids[NE * CAP];
__device__ float        g_tsc[NE * CAP];
__device__ float        g_H [(size_t)NE * CAP * NCAT];         // expert pre-act (fp32)
__device__ float        g_Hs[(size_t)N_TOK * NCAT_SH];         // shared pre-act (fp32)

// ---------------- small helpers ----------------
__device__ __forceinline__ float silu_f(float x) { return x / (1.0f + __expf(-x)); }

__device__ __forceinline__ uint32_t smem_u32(const void* p) {
    uint32_t a;
    asm("{ .reg .u64 t; cvta.to.shared.u64 t, %1; cvt.u32.u64 %0, t; }" : "=r"(a) : "l"(p));
    return a;
}

__device__ __forceinline__ uint32_t pack_bf2(float a, float b) {
    __nv_bfloat162 t = __floats2bfloat162_rn(a, b);
    return *reinterpret_cast<uint32_t*>(&t);
}
// split 8 fp32 -> bf16 hi granule (16B) + bf16 lo granule (16B)
__device__ __forceinline__ void split8(const float* f, uint4& hi, uint4& lo) {
    float h[8], l[8];
#pragma unroll
    for (int i = 0; i < 8; i++) {
        float hh = __bfloat162float(__float2bfloat16(f[i]));
        h[i] = hh;
        l[i] = f[i] - hh;
    }
    hi = make_uint4(pack_bf2(h[0], h[1]), pack_bf2(h[2], h[3]),
                    pack_bf2(h[4], h[5]), pack_bf2(h[6], h[7]));
    lo = make_uint4(pack_bf2(l[0], l[1]), pack_bf2(l[2], l[3]),
                    pack_bf2(l[4], l[5]), pack_bf2(l[6], l[7]));
}

__device__ __forceinline__ void ldsm4(uint32_t* r, uint32_t a) {
    asm volatile("ldmatrix.sync.aligned.m8n8.x4.shared.b16 {%0,%1,%2,%3}, [%4];"
                 : "=r"(r[0]), "=r"(r[1]), "=r"(r[2]), "=r"(r[3]) : "r"(a));
}
__device__ __forceinline__ void mma16816(float* d, const uint32_t* a,
                                         uint32_t b0, uint32_t b1) {
    asm volatile(
        "mma.sync.aligned.m16n8k16.row.col.f32.bf16.bf16.f32 "
        "{%0,%1,%2,%3}, {%4,%5,%6,%7}, {%8,%9}, {%0,%1,%2,%3};"
        : "+f"(d[0]), "+f"(d[1]), "+f"(d[2]), "+f"(d[3])
        : "r"(a[0]), "r"(a[1]), "r"(a[2]), "r"(a[3]), "r"(b0), "r"(b1));
}

// ---------------- routing kernels ----------------
__global__ void init_kernel() {
    if (threadIdx.x < NE) g_cnt[threadIdx.x] = 0;
}

__global__ void gate_kernel(const float* __restrict__ x, const float* __restrict__ gw) {
    __shared__ float sgw[NE * DIM];
    for (int i = threadIdx.x; i < NE * DIM; i += blockDim.x) sgw[i] = gw[i];
    __syncthreads();
    int warp = threadIdx.x >> 5, lane = threadIdx.x & 31;
    int t = blockIdx.x * 8 + warp;
    const float* xr = x + (size_t)t * DIM;
    float p[NE];
#pragma unroll
    for (int e = 0; e < NE; e++) p[e] = 0.0f;
    for (int d = lane; d < DIM; d += 32) {
        float xv = xr[d];
#pragma unroll
        for (int e = 0; e < NE; e++) p[e] += xv * sgw[e * DIM + d];
    }
#pragma unroll
    for (int e = 0; e < NE; e++) {
        float v = p[e];
        v += __shfl_xor_sync(0xffffffffu, v, 16);
        v += __shfl_xor_sync(0xffffffffu, v, 8);
        v += __shfl_xor_sync(0xffffffffu, v, 4);
        v += __shfl_xor_sync(0xffffffffu, v, 2);
        v += __shfl_xor_sync(0xffffffffu, v, 1);
        p[e] = v;
    }
    if (lane == 0) {
#pragma unroll
        for (int e = 0; e < NE; e++)
            g_scores[(size_t)e * N_TOK + t] = 1.0f / (1.0f + __expf(-p[e]));
    }
}

__global__ void select_kernel() {
    __shared__ unsigned int hist[256];
    __shared__ unsigned int s_prefix, s_mask;
    __shared__ int s_k;
    int e = blockIdx.x;
    const float* sc = g_scores + (size_t)e * N_TOK;
    if (threadIdx.x == 0) { s_prefix = 0u; s_mask = 0u; s_k = CAP; }
    for (int pass = 3; pass >= 0; pass--) {
        int shift = pass * 8;
        if (threadIdx.x < 256) hist[threadIdx.x] = 0u;
        __syncthreads();
        unsigned int prefix = s_prefix, mask = s_mask;
        for (int t = threadIdx.x; t < N_TOK; t += blockDim.x) {
            unsigned int b = __float_as_uint(sc[t]);
            if ((b & mask) == prefix) atomicAdd(&hist[(b >> shift) & 255u], 1u);
        }
        __syncthreads();
        if (threadIdx.x == 0) {
            int k = s_k, cum = 0, bin = 0;
            for (int i = 255; i >= 0; i--) {
                if (cum + (int)hist[i] >= k) { bin = i; s_k = k - cum; break; }
                cum += (int)hist[i];
            }
            s_prefix = prefix | ((unsigned)bin << shift);
            s_mask   = mask   | (0xFFu << shift);
        }
        __syncthreads();
    }
    if (threadIdx.x == 0) g_thresh[e] = s_prefix;
}

__global__ void compact_kernel() {
    int e = blockIdx.y;
    int t = blockIdx.x * 256 + threadIdx.x;
    float s = g_scores[(size_t)e * N_TOK + t];
    if (__float_as_uint(s) > g_thresh[e]) {
        int p = atomicAdd(&g_cnt[e], 1);
        g_ids[e * CAP + p] = t;
        g_tsc[e * CAP + p] = s;
    }
}

__global__ void tiefill_kernel() {
    int e = threadIdx.x >> 5, lane = threadIdx.x & 31;
    unsigned int th = g_thresh[e];
    int base = g_cnt[e];
    int need = CAP - base;
    const float* sc = g_scores + (size_t)e * N_TOK;
    int filled = 0;
    for (int t0 = 0; t0 < N_TOK && filled < need; t0 += 32) {
        unsigned int b = __float_as_uint(sc[t0 + lane]);
        unsigned int m = __ballot_sync(0xffffffffu, b == th);
        int before = __popc(m & ((1u << lane) - 1u));
        if (b == th && filled + before < need) {
            g_ids[e * CAP + base + filled + before] = t0 + lane;
            g_tsc[e * CAP + base + filled + before] = sc[t0 + lane];
        }
        filled += __popc(m);
    }
}

// ---------------- mma.sync bf16 3-term split GEMM ----------------
// MODE 0: expert up/gate : A = x[g_ids],        B = Wg|Wu,   OUT = g_H raw fp32
// MODE 1: expert down    : A = silu-fused g_H,  B = Wd,      OUT = score * atomicAdd(y)
// MODE 2: shared up/gate : A = x,               B = Wsg|Wsu, OUT = g_Hs raw fp32
// MODE 3: shared down    : A = silu-fused g_Hs, B = Wsd,     OUT = y (plain store)
constexpr int BM = 128, BN = 128, BK = 32;
// smem buffer layout (bytes): [Ahi 8K][Alo 8K][Bhi 8K][Blo 8K]
// each plane: [chunk(2)][row(128)][16 bf16 = 32B], swizzled: addr ^= (row&4)<<2
constexpr int PL_AHI = 0, PL_ALO = 8192, PL_BHI = 16384, PL_BLO = 24576;
constexpr int BUFB  = 32768;
constexpr int DSMEM = 2 * BUFB + 1024;

template <int MODE>
__global__ void __launch_bounds__(256, 1)
mma_gemm(const float* __restrict__ X, const float* __restrict__ B0,
         const float* __restrict__ B1, float* __restrict__ Y)
{
    constexpr int K    = (MODE == 0) ? DIM : (MODE == 1) ? F_EXP : (MODE == 2) ? DIM : F_SH;
    constexpr int KI   = K / BK;
    constexpr int UOFF = (MODE == 1) ? F_EXP : F_SH;

    extern __shared__ char dyn_raw[];
    char* dyn = (char*)(((uintptr_t)dyn_raw + 1023) & ~(uintptr_t)1023);
    const uint32_t sb = smem_u32(dyn);

    const int e    = blockIdx.z;
    const int m0   = blockIdx.y * BM;
    const int n0   = blockIdx.x * BN;
    const int tid  = threadIdx.x;
    const int lane = tid & 31;
    const int wid  = tid >> 5;
    const int wm   = wid >> 1;     // 0..3  (M warp)
    const int wn   = wid & 1;      // 0..1  (N warp)

    // ---------- loader geometry: thread -> (row, 16 consecutive k floats) ----
    const int arow = tid >> 1;
    const int ak   = (tid & 1) * 16;

    const float* aptr;
    if constexpr (MODE == 0)
        aptr = X + (size_t)g_ids[e * CAP + m0 + arow] * DIM + ak;
    else if constexpr (MODE == 2)
        aptr = X + (size_t)(m0 + arow) * DIM + ak;
    else if constexpr (MODE == 1)
        aptr = g_H + ((size_t)e * CAP + m0 + arow) * (size_t)NCAT + ak;
    else
        aptr = g_Hs + (size_t)(m0 + arow) * NCAT_SH + ak;

    const float* bptr;
    {
        int n = n0 + arow;
        if constexpr (MODE == 0)
            bptr = (n < F_EXP) ? B0 + ((size_t)e * F_EXP + n) * DIM + ak
                               : B1 + ((size_t)e * F_EXP + (n - F_EXP)) * DIM + ak;
        else if constexpr (MODE == 1)
            bptr = B0 + ((size_t)e * DIM + n) * (size_t)F_EXP + ak;
        else if constexpr (MODE == 2)
            bptr = (n < F_SH) ? B0 + (size_t)n * DIM + ak
                              : B1 + (size_t)(n - F_SH) * DIM + ak;
        else
            bptr = B0 + (size_t)n * F_SH + ak;
    }

    // smem store offsets for this thread's two 16B granules (within a plane)
    int sto[2];
#pragma unroll
    for (int g2 = 0; g2 < 2; g2++) {
        int o = (tid & 1) * 4096 + arow * 32 + g2 * 16;
        sto[g2] = o ^ ((arow & 4) << 2);
    }

    // ldmatrix per-lane offsets (within a plane+chunk)
    int offA[2], offB[4];
#pragma unroll
    for (int mt = 0; mt < 2; mt++) {
        int r = wm * 32 + mt * 16 + (lane & 15);
        offA[mt] = (r * 32 + (lane >> 4) * 16) ^ ((r & 4) << 2);
    }
#pragma unroll
    for (int np = 0; np < 4; np++) {
        int r = wn * 64 + np * 16 + (lane & 15);
        offB[np] = (r * 32 + (lane >> 4) * 16) ^ ((r & 4) << 2);
    }

    float acc[2][8][4];
#pragma unroll
    for (int i = 0; i < 2; i++)
#pragma unroll
        for (int j = 0; j < 8; j++)
#pragma unroll
            for (int k = 0; k < 4; k++) acc[i][j][k] = 0.0f;

    // ---------- prefetch registers ----------
    float4 pa0, pa1, pa2, pa3;          // A (gate part for down-modes)
    float4 pu0, pu1, pu2, pu3;          // A up part (down-modes only)
    float4 pb0, pb1, pb2, pb3;          // B

    auto prefetch = [&](int k0) {
        pa0 = *(const float4*)(aptr + k0);
        pa1 = *(const float4*)(aptr + k0 + 4);
        pa2 = *(const float4*)(aptr + k0 + 8);
        pa3 = *(const float4*)(aptr + k0 + 12);
        if constexpr (MODE == 1 || MODE == 3) {
            pu0 = *(const float4*)(aptr + k0 + UOFF);
            pu1 = *(const float4*)(aptr + k0 + UOFF + 4);
            pu2 = *(const float4*)(aptr + k0 + UOFF + 8);
            pu3 = *(const float4*)(aptr + k0 + UOFF + 12);
        }
        pb0 = *(const float4*)(bptr + k0);
        pb1 = *(const float4*)(bptr + k0 + 4);
        pb2 = *(const float4*)(bptr + k0 + 8);
        pb3 = *(const float4*)(bptr + k0 + 12);
    };

    auto stob = [&](char* bb) {
        float f[16];
        if constexpr (MODE == 0 || MODE == 2) {
            f[0] = pa0.x; f[1] = pa0.y; f[2] = pa0.z; f[3] = pa0.w;
            f[4] = pa1.x; f[5] = pa1.y; f[6] = pa1.z; f[7] = pa1.w;
            f[8] = pa2.x; f[9] = pa2.y; f[10] = pa2.z; f[11] = pa2.w;
            f[12] = pa3.x; f[13] = pa3.y; f[14] = pa3.z; f[15] = pa3.w;
        } else {
            f[0]  = silu_f(pa0.x) * pu0.x; f[1]  = silu_f(pa0.y) * pu0.y;
            f[2]  = silu_f(pa0.z) * pu0.z; f[3]  = silu_f(pa0.w) * pu0.w;
            f[4]  = silu_f(pa1.x) * pu1.x; f[5]  = silu_f(pa1.y) * pu1.y;
            f[6]  = silu_f(pa1.z) * pu1.z; f[7]  = silu_f(pa1.w) * pu1.w;
            f[8]  = silu_f(pa2.x) * pu2.x; f[9]  = silu_f(pa2.y) * pu2.y;
            f[10] = silu_f(pa2.z) * pu2.z; f[11] = silu_f(pa2.w) * pu2.w;
            f[12] = silu_f(pa3.x) * pu3.x; f[13] = silu_f(pa3.y) * pu3.y;
            f[14] = silu_f(pa3.z) * pu3.z; f[15] = silu_f(pa3.w) * pu3.w;
        }
        uint4 h0, l0, h1, l1;
        split8(f, h0, l0); split8(f + 8, h1, l1);
        *(uint4*)(bb + PL_AHI + sto[0]) = h0;
        *(uint4*)(bb + PL_AHI + sto[1]) = h1;
        *(uint4*)(bb + PL_ALO + sto[0]) = l0;
        *(uint4*)(bb + PL_ALO + sto[1]) = l1;

        float fb[16] = {pb0.x, pb0.y, pb0.z, pb0.w, pb1.x, pb1.y, pb1.z, pb1.w,
                        pb2.x, pb2.y, pb2.z, pb2.w, pb3.x, pb3.y, pb3.z, pb3.w};
        split8(fb, h0, l0); split8(fb + 8, h1, l1);
        *(uint4*)(bb + PL_BHI + sto[0]) = h0;
        *(uint4*)(bb + PL_BHI + sto[1]) = h1;
        *(uint4*)(bb + PL_BLO + sto[0]) = l0;
        *(uint4*)(bb + PL_BLO + sto[1]) = l1;
    };

    auto compute = [&](uint32_t bufaddr) {
#pragma unroll
        for (int c = 0; c < 2; c++) {
            uint32_t base = bufaddr + c * 4096;
            uint32_t ah[2][4], al[2][4];
#pragma unroll
            for (int mt = 0; mt < 2; mt++) {
                ldsm4(ah[mt], base + PL_AHI + offA[mt]);
                ldsm4(al[mt], base + PL_ALO + offA[mt]);
            }
#pragma unroll
            for (int np = 0; np < 4; np++) {
                uint32_t bh[4], bl[4];
                ldsm4(bh, base + PL_BHI + offB[np]);
                ldsm4(bl, base + PL_BLO + offB[np]);
#pragma unroll
                for (int mt = 0; mt < 2; mt++) {
                    mma16816(acc[mt][2 * np],     ah[mt], bh[0], bh[2]);
                    mma16816(acc[mt][2 * np],     ah[mt], bl[0], bl[2]);
                    mma16816(acc[mt][2 * np],     al[mt], bh[0], bh[2]);
                    mma16816(acc[mt][2 * np + 1], ah[mt], bh[1], bh[3]);
                    mma16816(acc[mt][2 * np + 1], ah[mt], bl[1], bl[3]);
                    mma16816(acc[mt][2 * np + 1], al[mt], bh[1], bh[3]);
                }
            }
        }
    };

    // ---------- pipelined main loop ----------
    prefetch(0);
    stob(dyn);
    __syncthreads();

    for (int it = 0; it < KI; ++it) {
        if (it + 1 < KI) prefetch((it + 1) * BK);
        compute(sb + (it & 1) * BUFB);
        if (it + 1 < KI) {
            __syncthreads();
            stob(dyn + ((it + 1) & 1) * BUFB);
            __syncthreads();
        }
    }

    // ---------- epilogue ----------
    const int gg = lane >> 2, tt = lane & 3;
#pragma unroll
    for (int mt = 0; mt < 2; mt++) {
        int r0   = m0 + wm * 32 + mt * 16 + gg;
        int colb = n0 + wn * 64 + tt * 2;
        if constexpr (MODE == 1) {
            int i0 = e * CAP + r0, i1 = i0 + 8;
            int tok0 = g_ids[i0]; float s0 = g_tsc[i0];
            int tok1 = g_ids[i1]; float s1 = g_tsc[i1];
            float* y0 = Y + (size_t)tok0 * DIM + colb;
            float* y1 = Y + (size_t)tok1 * DIM + colb;
#pragma unroll
            for (int n8 = 0; n8 < 8; n8++) {
                atomicAdd(y0 + n8 * 8,     acc[mt][n8][0] * s0);
                atomicAdd(y0 + n8 * 8 + 1, acc[mt][n8][1] * s0);
                atomicAdd(y1 + n8 * 8,     acc[mt][n8][2] * s1);
                atomicAdd(y1 + n8 * 8 + 1, acc[mt][n8][3] * s1);
            }
        } else {
            float *o0, *o1;
            if constexpr (MODE == 0) {
                o0 = g_H + ((size_t)e * CAP + r0) * (size_t)NCAT + colb;
                o1 = o0 + 8 * (size_t)NCAT;
            } else if constexpr (MODE == 2) {
                o0 = g_Hs + (size_t)r0 * NCAT_SH + colb;
                o1 = o0 + 8 * NCAT_SH;
            } else {
                o0 = Y + (size_t)r0 * DIM + colb;
                o1 = o0 + 8 * DIM;
            }
#pragma unroll
            for (int n8 = 0; n8 < 8; n8++) {
                *(float2*)(o0 + n8 * 8) = make_float2(acc[mt][n8][0], acc[mt][n8][1]);
                *(float2*)(o1 + n8 * 8) = make_float2(acc[mt][n8][2], acc[mt][n8][3]);
            }
        }
    }
}

// ---------------- launch ----------------
extern "C" void kernel_launch(void* const* d_in, const int* in_sizes, int n_in,
                              void* d_out, int out_size) {
    const float* x   = (const float*)d_in[0];
    const float* gw  = (const float*)d_in[1];
    const float* Wg  = (const float*)d_in[2];
    const float* Wu  = (const float*)d_in[3];
    const float* Wd  = (const float*)d_in[4];
    const float* Wsg = (const float*)d_in[5];
    const float* Wsu = (const float*)d_in[6];
    const float* Wsd = (const float*)d_in[7];
    float* y = (float*)d_out;

    cudaFuncSetAttribute(mma_gemm<0>, cudaFuncAttributeMaxDynamicSharedMemorySize, DSMEM);
    cudaFuncSetAttribute(mma_gemm<1>, cudaFuncAttributeMaxDynamicSharedMemorySize, DSMEM);
    cudaFuncSetAttribute(mma_gemm<2>, cudaFuncAttributeMaxDynamicSharedMemorySize, DSMEM);
    cudaFuncSetAttribute(mma_gemm<3>, cudaFuncAttributeMaxDynamicSharedMemorySize, DSMEM);

    init_kernel<<<1, 32>>>();
    gate_kernel<<<N_TOK / 8, 256>>>(x, gw);
    select_kernel<<<NE, 1024>>>();
    compact_kernel<<<dim3(N_TOK / 256, NE), 256>>>();
    tiefill_kernel<<<1, NE * 32>>>();

    // shared expert (dense write of y -> serves as init)
    mma_gemm<2><<<dim3(NCAT_SH / BN, N_TOK / BM, 1), 256, DSMEM>>>(x, Wsg, Wsu, nullptr);
    mma_gemm<3><<<dim3(DIM / BN, N_TOK / BM, 1), 256, DSMEM>>>(nullptr, Wsd, nullptr, y);

    // routed experts (atomicAdd combine into y)
    mma_gemm<0><<<dim3(NCAT / BN, CAP / BM, NE), 256, DSMEM>>>(x, Wg, Wu, nullptr);
    mma_gemm<1><<<dim3(DIM / BN, CAP / BM, NE), 256, DSMEM>>>(nullptr, Wd, nullptr, y);
}

// round 8
// speedup vs baseline: 1.0030x; 1.0030x over previous
#include <cuda_runtime.h>
#include <cuda_bf16.h>
#include <cstdint>
#include <cstddef>

// ---------------- problem constants ----------------
#define N_TOK   32768      // B*L
#define DIM     768
#define NE      16         // experts
#define CAP     4096       // capacity per expert
#define F_EXP   3072
#define NCAT    6144       // 2*F_EXP (gate|up concat)
#define F_SH    1536
#define NCAT_SH 3072       // 2*F_SH

// ---------------- scratch (device globals; no allocations allowed) ----------
__device__ float        g_scores[(size_t)NE * N_TOK];          // [e][t]
__device__ unsigned int g_thresh[NE];
__device__ int          g_cnt[NE];
__device__ int          g_ids[NE * CAP];
__device__ float        g_tsc[NE * CAP];
__device__ float        g_H [(size_t)NE * CAP * NCAT];         // expert pre-act (fp32)
__device__ float        g_Hs[(size_t)N_TOK * NCAT_SH];         // shared pre-act (fp32)

// ---------------- small helpers ----------------
__device__ __forceinline__ float silu_f(float x) { return x / (1.0f + __expf(-x)); }

__device__ __forceinline__ uint32_t smem_u32(const void* p) {
    uint32_t a;
    asm("{ .reg .u64 t; cvta.to.shared.u64 t, %1; cvt.u32.u64 %0, t; }" : "=r"(a) : "l"(p));
    return a;
}

__device__ __forceinline__ uint32_t pack_bf2(float a, float b) {
    __nv_bfloat162 t = __floats2bfloat162_rn(a, b);
    return *reinterpret_cast<uint32_t*>(&t);
}
// split 8 fp32 -> bf16 hi granule (16B) + bf16 lo granule (16B)
__device__ __forceinline__ void split8(const float* f, uint4& hi, uint4& lo) {
    float h[8], l[8];
#pragma unroll
    for (int i = 0; i < 8; i++) {
        float hh = __bfloat162float(__float2bfloat16(f[i]));
        h[i] = hh;
        l[i] = f[i] - hh;
    }
    hi = make_uint4(pack_bf2(h[0], h[1]), pack_bf2(h[2], h[3]),
                    pack_bf2(h[4], h[5]), pack_bf2(h[6], h[7]));
    lo = make_uint4(pack_bf2(l[0], l[1]), pack_bf2(l[2], l[3]),
                    pack_bf2(l[4], l[5]), pack_bf2(l[6], l[7]));
}

__device__ __forceinline__ void ldsm4(uint32_t* r, uint32_t a) {
    asm volatile("ldmatrix.sync.aligned.m8n8.x4.shared.b16 {%0,%1,%2,%3}, [%4];"
                 : "=r"(r[0]), "=r"(r[1]), "=r"(r[2]), "=r"(r[3]) : "r"(a));
}
__device__ __forceinline__ void mma16816(float* d, const uint32_t* a,
                                         uint32_t b0, uint32_t b1) {
    asm volatile(
        "mma.sync.aligned.m16n8k16.row.col.f32.bf16.bf16.f32 "
        "{%0,%1,%2,%3}, {%4,%5,%6,%7}, {%8,%9}, {%0,%1,%2,%3};"
        : "+f"(d[0]), "+f"(d[1]), "+f"(d[2]), "+f"(d[3])
        : "r"(a[0]), "r"(a[1]), "r"(a[2]), "r"(a[3]), "r"(b0), "r"(b1));
}

// ---------------- routing kernels ----------------
__global__ void init_kernel() {
    if (threadIdx.x < NE) g_cnt[threadIdx.x] = 0;
}

__global__ void gate_kernel(const float* __restrict__ x, const float* __restrict__ gw) {
    __shared__ float sgw[NE * DIM];
    for (int i = threadIdx.x; i < NE * DIM; i += blockDim.x) sgw[i] = gw[i];
    __syncthreads();
    int warp = threadIdx.x >> 5, lane = threadIdx.x & 31;
    int t = blockIdx.x * 8 + warp;
    const float* xr = x + (size_t)t * DIM;
    float p[NE];
#pragma unroll
    for (int e = 0; e < NE; e++) p[e] = 0.0f;
    for (int d = lane; d < DIM; d += 32) {
        float xv = xr[d];
#pragma unroll
        for (int e = 0; e < NE; e++) p[e] += xv * sgw[e * DIM + d];
    }
#pragma unroll
    for (int e = 0; e < NE; e++) {
        float v = p[e];
        v += __shfl_xor_sync(0xffffffffu, v, 16);
        v += __shfl_xor_sync(0xffffffffu, v, 8);
        v += __shfl_xor_sync(0xffffffffu, v, 4);
        v += __shfl_xor_sync(0xffffffffu, v, 2);
        v += __shfl_xor_sync(0xffffffffu, v, 1);
        p[e] = v;
    }
    if (lane == 0) {
#pragma unroll
        for (int e = 0; e < NE; e++)
            g_scores[(size_t)e * N_TOK + t] = 1.0f / (1.0f + __expf(-p[e]));
    }
}

__global__ void select_kernel() {
    __shared__ unsigned int hist[256];
    __shared__ unsigned int s_prefix, s_mask;
    __shared__ int s_k;
    int e = blockIdx.x;
    const float* sc = g_scores + (size_t)e * N_TOK;
    if (threadIdx.x == 0) { s_prefix = 0u; s_mask = 0u; s_k = CAP; }
    for (int pass = 3; pass >= 0; pass--) {
        int shift = pass * 8;
        if (threadIdx.x < 256) hist[threadIdx.x] = 0u;
        __syncthreads();
        unsigned int prefix = s_prefix, mask = s_mask;
        for (int t = threadIdx.x; t < N_TOK; t += blockDim.x) {
            unsigned int b = __float_as_uint(sc[t]);
            if ((b & mask) == prefix) atomicAdd(&hist[(b >> shift) & 255u], 1u);
        }
        __syncthreads();
        if (threadIdx.x == 0) {
            int k = s_k, cum = 0, bin = 0;
            for (int i = 255; i >= 0; i--) {
                if (cum + (int)hist[i] >= k) { bin = i; s_k = k - cum; break; }
                cum += (int)hist[i];
            }
            s_prefix = prefix | ((unsigned)bin << shift);
            s_mask   = mask   | (0xFFu << shift);
        }
        __syncthreads();
    }
    if (threadIdx.x == 0) g_thresh[e] = s_prefix;
}

__global__ void compact_kernel() {
    int e = blockIdx.y;
    int t = blockIdx.x * 256 + threadIdx.x;
    float s = g_scores[(size_t)e * N_TOK + t];
    if (__float_as_uint(s) > g_thresh[e]) {
        int p = atomicAdd(&g_cnt[e], 1);
        g_ids[e * CAP + p] = t;
        g_tsc[e * CAP + p] = s;
    }
}

__global__ void tiefill_kernel() {
    int e = threadIdx.x >> 5, lane = threadIdx.x & 31;
    unsigned int th = g_thresh[e];
    int base = g_cnt[e];
    int need = CAP - base;
    const float* sc = g_scores + (size_t)e * N_TOK;
    int filled = 0;
    for (int t0 = 0; t0 < N_TOK && filled < need; t0 += 32) {
        unsigned int b = __float_as_uint(sc[t0 + lane]);
        unsigned int m = __ballot_sync(0xffffffffu, b == th);
        int before = __popc(m & ((1u << lane) - 1u));
        if (b == th && filled + before < need) {
            g_ids[e * CAP + base + filled + before] = t0 + lane;
            g_tsc[e * CAP + base + filled + before] = sc[t0 + lane];
        }
        filled += __popc(m);
    }
}

// ---------------- mma.sync bf16 3-term split GEMM ----------------
// MODE 0: expert up/gate : A = x[g_ids],        B = Wg|Wu,   OUT = g_H raw fp32
// MODE 1: expert down    : A = silu-fused g_H,  B = Wd,      OUT = score * atomicAdd(y)
// MODE 2: shared up/gate : A = x,               B = Wsg|Wsu, OUT = g_Hs raw fp32
// MODE 3: shared down    : A = silu-fused g_Hs, B = Wsd,     OUT = y (plain store)
constexpr int BM = 128, BN = 128, BK = 32;
// smem buffer layout (bytes): [Ahi 8K][Alo 8K][Bhi 8K][Blo 8K]
// each plane: [chunk(2)][row(128)][16 bf16 = 32B], swizzled: addr ^= (row&4)<<2
constexpr int PL_AHI = 0, PL_ALO = 8192, PL_BHI = 16384, PL_BLO = 24576;
constexpr int BUFB  = 32768;
constexpr int DSMEM = 2 * BUFB + 1024;

template <int MODE>
__global__ void __launch_bounds__(256, 1)
mma_gemm(const float* __restrict__ X, const float* __restrict__ B0,
         const float* __restrict__ B1, float* __restrict__ Y)
{
    constexpr int K    = (MODE == 0) ? DIM : (MODE == 1) ? F_EXP : (MODE == 2) ? DIM : F_SH;
    constexpr int KI   = K / BK;
    constexpr int UOFF = (MODE == 1) ? F_EXP : F_SH;

    extern __shared__ char dyn_raw[];
    char* dyn = (char*)(((uintptr_t)dyn_raw + 1023) & ~(uintptr_t)1023);
    const uint32_t sb = smem_u32(dyn);

    const int e    = blockIdx.z;
    const int m0   = blockIdx.y * BM;
    const int n0   = blockIdx.x * BN;
    const int tid  = threadIdx.x;
    const int lane = tid & 31;
    const int wid  = tid >> 5;
    const int wm   = wid >> 1;     // 0..3  (M warp)
    const int wn   = wid & 1;      // 0..1  (N warp)

    // ---------- loader geometry: thread -> (row, 16 consecutive k floats) ----
    const int arow = tid >> 1;
    const int ak   = (tid & 1) * 16;

    const float* aptr;
    if constexpr (MODE == 0)
        aptr = X + (size_t)g_ids[e * CAP + m0 + arow] * DIM + ak;
    else if constexpr (MODE == 2)
        aptr = X + (size_t)(m0 + arow) * DIM + ak;
    else if constexpr (MODE == 1)
        aptr = g_H + ((size_t)e * CAP + m0 + arow) * (size_t)NCAT + ak;
    else
        aptr = g_Hs + (size_t)(m0 + arow) * NCAT_SH + ak;

    const float* bptr;
    {
        int n = n0 + arow;
        if constexpr (MODE == 0)
            bptr = (n < F_EXP) ? B0 + ((size_t)e * F_EXP + n) * DIM + ak
                               : B1 + ((size_t)e * F_EXP + (n - F_EXP)) * DIM + ak;
        else if constexpr (MODE == 1)
            bptr = B0 + ((size_t)e * DIM + n) * (size_t)F_EXP + ak;
        else if constexpr (MODE == 2)
            bptr = (n < F_SH) ? B0 + (size_t)n * DIM + ak
                              : B1 + (size_t)(n - F_SH) * DIM + ak;
        else
            bptr = B0 + (size_t)n * F_SH + ak;
    }

    // smem store offsets for this thread's two 16B granules (within a plane)
    int sto[2];
#pragma unroll
    for (int g2 = 0; g2 < 2; g2++) {
        int o = (tid & 1) * 4096 + arow * 32 + g2 * 16;
        sto[g2] = o ^ ((arow & 4) << 2);
    }

    // ldmatrix per-lane offsets (within a plane+chunk)
    int offA[2], offB[4];
#pragma unroll
    for (int mt = 0; mt < 2; mt++) {
        int r = wm * 32 + mt * 16 + (lane & 15);
        offA[mt] = (r * 32 + (lane >> 4) * 16) ^ ((r & 4) << 2);
    }
#pragma unroll
    for (int np = 0; np < 4; np++) {
        int r = wn * 64 + np * 16 + (lane & 15);
        offB[np] = (r * 32 + (lane >> 4) * 16) ^ ((r & 4) << 2);
    }

    float acc[2][8][4];
#pragma unroll
    for (int i = 0; i < 2; i++)
#pragma unroll
        for (int j = 0; j < 8; j++)
#pragma unroll
            for (int k = 0; k < 4; k++) acc[i][j][k] = 0.0f;

    // ---------- prefetch registers ----------
    float4 pa0, pa1, pa2, pa3;          // A (gate part for down-modes)
    float4 pu0, pu1, pu2, pu3;          // A up part (down-modes only)
    float4 pb0, pb1, pb2, pb3;          // B

    auto prefetch = [&](int k0) {
        pa0 = *(const float4*)(aptr + k0);
        pa1 = *(const float4*)(aptr + k0 + 4);
        pa2 = *(const float4*)(aptr + k0 + 8);
        pa3 = *(const float4*)(aptr + k0 + 12);
        if constexpr (MODE == 1 || MODE == 3) {
            pu0 = *(const float4*)(aptr + k0 + UOFF);
            pu1 = *(const float4*)(aptr + k0 + UOFF + 4);
            pu2 = *(const float4*)(aptr + k0 + UOFF + 8);
            pu3 = *(const float4*)(aptr + k0 + UOFF + 12);
        }
        pb0 = *(const float4*)(bptr + k0);
        pb1 = *(const float4*)(bptr + k0 + 4);
        pb2 = *(const float4*)(bptr + k0 + 8);
        pb3 = *(const float4*)(bptr + k0 + 12);
    };

    auto stob = [&](char* bb) {
        float f[16];
        if constexpr (MODE == 0 || MODE == 2) {
            f[0] = pa0.x; f[1] = pa0.y; f[2] = pa0.z; f[3] = pa0.w;
            f[4] = pa1.x; f[5] = pa1.y; f[6] = pa1.z; f[7] = pa1.w;
            f[8] = pa2.x; f[9] = pa2.y; f[10] = pa2.z; f[11] = pa2.w;
            f[12] = pa3.x; f[13] = pa3.y; f[14] = pa3.z; f[15] = pa3.w;
        } else {
            f[0]  = silu_f(pa0.x) * pu0.x; f[1]  = silu_f(pa0.y) * pu0.y;
            f[2]  = silu_f(pa0.z) * pu0.z; f[3]  = silu_f(pa0.w) * pu0.w;
            f[4]  = silu_f(pa1.x) * pu1.x; f[5]  = silu_f(pa1.y) * pu1.y;
            f[6]  = silu_f(pa1.z) * pu1.z; f[7]  = silu_f(pa1.w) * pu1.w;
            f[8]  = silu_f(pa2.x) * pu2.x; f[9]  = silu_f(pa2.y) * pu2.y;
            f[10] = silu_f(pa2.z) * pu2.z; f[11] = silu_f(pa2.w) * pu2.w;
            f[12] = silu_f(pa3.x) * pu3.x; f[13] = silu_f(pa3.y) * pu3.y;
            f[14] = silu_f(pa3.z) * pu3.z; f[15] = silu_f(pa3.w) * pu3.w;
        }
        uint4 h0, l0, h1, l1;
        split8(f, h0, l0); split8(f + 8, h1, l1);
        *(uint4*)(bb + PL_AHI + sto[0]) = h0;
        *(uint4*)(bb + PL_AHI + sto[1]) = h1;
        *(uint4*)(bb + PL_ALO + sto[0]) = l0;
        *(uint4*)(bb + PL_ALO + sto[1]) = l1;

        float fb[16] = {pb0.x, pb0.y, pb0.z, pb0.w, pb1.x, pb1.y, pb1.z, pb1.w,
                        pb2.x, pb2.y, pb2.z, pb2.w, pb3.x, pb3.y, pb3.z, pb3.w};
        split8(fb, h0, l0); split8(fb + 8, h1, l1);
        *(uint4*)(bb + PL_BHI + sto[0]) = h0;
        *(uint4*)(bb + PL_BHI + sto[1]) = h1;
        *(uint4*)(bb + PL_BLO + sto[0]) = l0;
        *(uint4*)(bb + PL_BLO + sto[1]) = l1;
    };

    auto compute = [&](uint32_t bufaddr) {
#pragma unroll
        for (int c = 0; c < 2; c++) {
            uint32_t base = bufaddr + c * 4096;
            uint32_t ah[2][4], al[2][4];
#pragma unroll
            for (int mt = 0; mt < 2; mt++) {
                ldsm4(ah[mt], base + PL_AHI + offA[mt]);
                ldsm4(al[mt], base + PL_ALO + offA[mt]);
            }
#pragma unroll
            for (int np = 0; np < 4; np++) {
                uint32_t bh[4], bl[4];
                ldsm4(bh, base + PL_BHI + offB[np]);
                ldsm4(bl, base + PL_BLO + offB[np]);
#pragma unroll
                for (int mt = 0; mt < 2; mt++) {
                    mma16816(acc[mt][2 * np],     ah[mt], bh[0], bh[2]);
                    mma16816(acc[mt][2 * np],     ah[mt], bl[0], bl[2]);
                    mma16816(acc[mt][2 * np],     al[mt], bh[0], bh[2]);
                    mma16816(acc[mt][2 * np + 1], ah[mt], bh[1], bh[3]);
                    mma16816(acc[mt][2 * np + 1], ah[mt], bl[1], bl[3]);
                    mma16816(acc[mt][2 * np + 1], al[mt], bh[1], bh[3]);
                }
            }
        }
    };

    // ---------- pipelined main loop ----------
    prefetch(0);
    stob(dyn);
    __syncthreads();

    for (int it = 0; it < KI; ++it) {
        if (it + 1 < KI) prefetch((it + 1) * BK);
        compute(sb + (it & 1) * BUFB);
        if (it + 1 < KI) {
            __syncthreads();
            stob(dyn + ((it + 1) & 1) * BUFB);
            __syncthreads();
        }
    }

    // ---------- epilogue ----------
    const int gg = lane >> 2, tt = lane & 3;
#pragma unroll
    for (int mt = 0; mt < 2; mt++) {
        int r0   = m0 + wm * 32 + mt * 16 + gg;
        int colb = n0 + wn * 64 + tt * 2;
        if constexpr (MODE == 1) {
            int i0 = e * CAP + r0, i1 = i0 + 8;
            int tok0 = g_ids[i0]; float s0 = g_tsc[i0];
            int tok1 = g_ids[i1]; float s1 = g_tsc[i1];
            float* y0 = Y + (size_t)tok0 * DIM + colb;
            float* y1 = Y + (size_t)tok1 * DIM + colb;
#pragma unroll
            for (int n8 = 0; n8 < 8; n8++) {
                atomicAdd(y0 + n8 * 8,     acc[mt][n8][0] * s0);
                atomicAdd(y0 + n8 * 8 + 1, acc[mt][n8][1] * s0);
                atomicAdd(y1 + n8 * 8,     acc[mt][n8][2] * s1);
                atomicAdd(y1 + n8 * 8 + 1, acc[mt][n8][3] * s1);
            }
        } else {
            float *o0, *o1;
            if constexpr (MODE == 0) {
                o0 = g_H + ((size_t)e * CAP + r0) * (size_t)NCAT + colb;
                o1 = o0 + 8 * (size_t)NCAT;
            } else if constexpr (MODE == 2) {
                o0 = g_Hs + (size_t)r0 * NCAT_SH + colb;
                o1 = o0 + 8 * NCAT_SH;
            } else {
                o0 = Y + (size_t)r0 * DIM + colb;
                o1 = o0 + 8 * DIM;
            }
#pragma unroll
            for (int n8 = 0; n8 < 8; n8++) {
                *(float2*)(o0 + n8 * 8) = make_float2(acc[mt][n8][0], acc[mt][n8][1]);
                *(float2*)(o1 + n8 * 8) = make_float2(acc[mt][n8][2], acc[mt][n8][3]);
            }
        }
    }
}

// ---------------- launch ----------------
extern "C" void kernel_launch(void* const* d_in, const int* in_sizes, int n_in,
                              void* d_out, int out_size) {
    const float* x   = (const float*)d_in[0];
    const float* gw  = (const float*)d_in[1];
    const float* Wg  = (const float*)d_in[2];
    const float* Wu  = (const float*)d_in[3];
    const float* Wd  = (const float*)d_in[4];
    const float* Wsg = (const float*)d_in[5];
    const float* Wsu = (const float*)d_in[6];
    const float* Wsd = (const float*)d_in[7];
    float* y = (float*)d_out;

    cudaFuncSetAttribute(mma_gemm<0>, cudaFuncAttributeMaxDynamicSharedMemorySize, DSMEM);
    cudaFuncSetAttribute(mma_gemm<1>, cudaFuncAttributeMaxDynamicSharedMemorySize, DSMEM);
    cudaFuncSetAttribute(mma_gemm<2>, cudaFuncAttributeMaxDynamicSharedMemorySize, DSMEM);
    cudaFuncSetAttribute(mma_gemm<3>, cudaFuncAttributeMaxDynamicSharedMemorySize, DSMEM);

    init_kernel<<<1, 32>>>();
    gate_kernel<<<N_TOK / 8, 256>>>(x, gw);
    select_kernel<<<NE, 1024>>>();
    compact_kernel<<<dim3(N_TOK / 256, NE), 256>>>();
    tiefill_kernel<<<1, NE * 32>>>();

    // shared expert (dense write of y -> serves as init)
    mma_gemm<2><<<dim3(NCAT_SH / BN, N_TOK / BM, 1), 256, DSMEM>>>(x, Wsg, Wsu, nullptr);
    mma_gemm<3><<<dim3(DIM / BN, N_TOK / BM, 1), 256, DSMEM>>>(nullptr, Wsd, nullptr, y);

    // routed experts (atomicAdd combine into y)
    mma_gemm<0><<<dim3(NCAT / BN, CAP / BM, NE), 256, DSMEM>>>(x, Wg, Wu, nullptr);
    mma_gemm<1><<<dim3(DIM / BN, CAP / BM, NE), 256, DSMEM>>>(nullptr, Wd, nullptr, y);
}